// round 7
// baseline (speedup 1.0000x reference)
#include <cuda_runtime.h>
#include <cstdint>

#define DM   128
#define SL   2048
#define NB   32
#define WIN  64
#define BAND (2*WIN-1)       // 127
#define WROW 132             // padded band row: [0]=0, [1..127]=w, [128]=0
#define NCH  16
#define CHL  (SL/NCH)        // 128
#define TI   32              // i-tile of band kernel
#define WR   (TI + 2*WIN - 2) // 158 j-window rows
#define AFT_SMEM ((2*WR*DM + TI*WROW)*4)  // 178688 B

typedef unsigned long long u64;

// ---------- scratch (device globals: allocation-free) ----------
__device__ float g_q[(size_t)NB*SL*DM];   // q, then y after k_aft
__device__ float g_k[(size_t)NB*SL*DM];   // k, then exp_k after k_expsum
__device__ float g_v[(size_t)NB*SL*DM];   // v, then u = exp_k*v
__device__ float g_w[(size_t)SL*WROW];
__device__ float g_c[SL];
__device__ float g_pmax[NB*NCH*DM];
__device__ float g_pse[NB*NCH*DM];
__device__ float g_psu[NB*NCH*DM];
__device__ float g_kmax[NB*DM];
__device__ float g_Se[NB*DM];
__device__ float g_Su[NB*DM];

// ---------- packed f32x2 helpers (FFMA2: 2x fp32 FMA per instruction) ----------
__device__ __forceinline__ u64 pack_dup(float x){
  u64 r; unsigned xi = __float_as_uint(x);
  asm("mov.b64 %0, {%1,%2};" : "=l"(r) : "r"(xi), "r"(xi));
  return r;
}
__device__ __forceinline__ u64 pack2(float x, float y){
  u64 r;
  asm("mov.b64 %0, {%1,%2};" : "=l"(r) : "r"(__float_as_uint(x)), "r"(__float_as_uint(y)));
  return r;
}
__device__ __forceinline__ float2 unpack2(u64 v){
  unsigned lo, hi;
  asm("mov.b64 {%0,%1}, %2;" : "=r"(lo), "=r"(hi) : "l"(v));
  return make_float2(__uint_as_float(lo), __uint_as_float(hi));
}
__device__ __forceinline__ void fma2(u64 &d, u64 a, u64 b){
  asm("fma.rn.f32x2 %0, %1, %2, %0;" : "+l"(d) : "l"(a), "l"(b));
}

// ---------------------------------------------------------------------------
// K1: QKV projection.  q/k/v[n,l,d] = sum_c x[n,c,l]*W[c,d] + b[d]
// Block: (l-tile of 64, batch, proj in {q,k,v}); 256 threads.
// Shared x-tile stored as [c][li] (stride 68) so li-pairs load as LDS.64.
// Thread: 4 consecutive d x 8 li (4 li-pairs) -> 16 f32x2 accumulators.
// ---------------------------------------------------------------------------
__global__ void __launch_bounds__(256, 2) k_proj(
    const float* __restrict__ x,
    const float* __restrict__ Wq, const float* __restrict__ bq,
    const float* __restrict__ Wk, const float* __restrict__ bk,
    const float* __restrict__ Wv, const float* __restrict__ bv)
{
  __shared__ float sh[DM*68];
  const int lt = blockIdx.x, n = blockIdx.y, p = blockIdx.z;
  const int l0 = lt*64;
  const float* W    = (p==0) ? Wq : (p==1 ? Wk : Wv);
  const float* bias = (p==0) ? bq : (p==1 ? bk : bv);
  float* out        = (p==0) ? g_q : (p==1 ? g_k : g_v);
  const int tid = threadIdx.x;

  // load x tile: x[n][c][l0..l0+63] -> sh[c][li]  (contiguous li: STS.128)
  const float* xb = x + ((size_t)n*DM)*SL + l0;
  #pragma unroll
  for (int itr = 0; itr < 8; itr++){
    int idx = itr*256 + tid;            // 0..2047
    int c = idx >> 4, l4 = (idx & 15)*4;
    float4 v4 = *(const float4*)(xb + (size_t)c*SL + l4);
    *(float4*)&sh[c*68 + l4] = v4;
  }
  __syncthreads();

  const int dg = tid & 31, lg = tid >> 5;
  const int d0 = dg*4, li0 = lg*8;
  u64 acc[4][4];  // [li-pair][d]
  #pragma unroll
  for (int a1=0;a1<4;a1++){
    #pragma unroll
    for (int b1=0;b1<4;b1++) acc[a1][b1] = 0ULL;
  }

  const float* Wp  = W + d0;
  const float* shx = sh + li0;
  #pragma unroll 4
  for (int c = 0; c < DM; c++){
    float4 w4 = *(const float4*)(Wp + (size_t)c*DM);
    u64 wd0 = pack_dup(w4.x), wd1 = pack_dup(w4.y), wd2 = pack_dup(w4.z), wd3 = pack_dup(w4.w);
    const u64* xp = (const u64*)(shx + c*68);
    u64 x0 = xp[0], x1 = xp[1], x2 = xp[2], x3 = xp[3];
    fma2(acc[0][0], x0, wd0); fma2(acc[0][1], x0, wd1); fma2(acc[0][2], x0, wd2); fma2(acc[0][3], x0, wd3);
    fma2(acc[1][0], x1, wd0); fma2(acc[1][1], x1, wd1); fma2(acc[1][2], x1, wd2); fma2(acc[1][3], x1, wd3);
    fma2(acc[2][0], x2, wd0); fma2(acc[2][1], x2, wd1); fma2(acc[2][2], x2, wd2); fma2(acc[2][3], x2, wd3);
    fma2(acc[3][0], x3, wd0); fma2(acc[3][1], x3, wd1); fma2(acc[3][2], x3, wd2); fma2(acc[3][3], x3, wd3);
  }

  float4 b4 = *(const float4*)(bias + d0);
  float* op = out + (((size_t)n*SL + l0 + li0)*DM + d0);
  #pragma unroll
  for (int pr = 0; pr < 4; pr++){
    float2 r0 = unpack2(acc[pr][0]);
    float2 r1 = unpack2(acc[pr][1]);
    float2 r2 = unpack2(acc[pr][2]);
    float2 r3 = unpack2(acc[pr][3]);
    *(float4*)(op + (size_t)(2*pr  )*DM) = make_float4(r0.x+b4.x, r1.x+b4.y, r2.x+b4.z, r3.x+b4.w);
    *(float4*)(op + (size_t)(2*pr+1)*DM) = make_float4(r0.y+b4.x, r1.y+b4.y, r2.y+b4.z, r3.y+b4.w);
  }
}

// ---------------------------------------------------------------------------
// K2a/K2b: column max of k over l, per (n,d)
// ---------------------------------------------------------------------------
__global__ void __launch_bounds__(128) k_colmax()
{
  const int n = blockIdx.x, ch = blockIdx.y, d = threadIdx.x;
  const float* kp = g_k + ((size_t)n*SL + ch*CHL)*DM + d;
  float m = -3.0e38f;
  #pragma unroll 8
  for (int l = 0; l < CHL; l++) m = fmaxf(m, kp[(size_t)l*DM]);
  g_pmax[(n*NCH + ch)*DM + d] = m;
}
__global__ void __launch_bounds__(128) k_colmax2()
{
  const int n = blockIdx.x, d = threadIdx.x;
  float m = -3.0e38f;
  #pragma unroll
  for (int ch = 0; ch < NCH; ch++) m = fmaxf(m, g_pmax[(n*NCH + ch)*DM + d]);
  g_kmax[n*DM + d] = m;
}

// ---------------------------------------------------------------------------
// K3a/K3b: e = exp(k - kmax), u = e*v (in place), plus column sums Se, Su
// ---------------------------------------------------------------------------
__global__ void __launch_bounds__(128) k_expsum()
{
  const int n = blockIdx.x, ch = blockIdx.y, d = threadIdx.x;
  const float km = g_kmax[n*DM + d];
  const size_t base = ((size_t)n*SL + ch*CHL)*DM + d;
  float se = 0.f, su = 0.f;
  #pragma unroll 4
  for (int l = 0; l < CHL; l++){
    size_t o = base + (size_t)l*DM;
    float e = __expf(g_k[o] - km);
    float u = e * g_v[o];
    g_k[o] = e; g_v[o] = u;
    se += e; su += u;
  }
  g_pse[(n*NCH + ch)*DM + d] = se;
  g_psu[(n*NCH + ch)*DM + d] = su;
}
__global__ void __launch_bounds__(128) k_sum2()
{
  const int n = blockIdx.x, d = threadIdx.x;
  float se = 0.f, su = 0.f;
  #pragma unroll
  for (int ch = 0; ch < NCH; ch++){
    se += g_pse[(n*NCH + ch)*DM + d];
    su += g_psu[(n*NCH + ch)*DM + d];
  }
  g_Se[n*DM + d] = se;
  g_Su[n*DM + d] = su;
}

// ---------------------------------------------------------------------------
// K4: band weights.  m_i = max(0, max_{|i-j|<64} pos_bias[i,j]);  c_i = exp(-m_i)
//     w[i][1+t] = exp(pb-m_i) - c_i for valid (t,j), 0 otherwise; w[i][0]=w[i][128]=0
// ---------------------------------------------------------------------------
__global__ void __launch_bounds__(128) k_pb(const float* __restrict__ pbias)
{
  __shared__ float red[128];
  const int i = blockIdx.x, t = threadIdx.x;
  const int j = i - (WIN-1) + t;
  const bool valid = (t < BAND) && (j >= 0) && (j < SL);
  float v = valid ? pbias[(size_t)i*SL + j] : -3.0e38f;
  red[t] = v;
  __syncthreads();
  #pragma unroll
  for (int s = 64; s > 0; s >>= 1){
    if (t < s) red[t] = fmaxf(red[t], red[t+s]);
    __syncthreads();
  }
  const float m = fmaxf(red[0], 0.f);
  const float c = __expf(-m);
  if (t == 0){
    g_c[i] = c;
    g_w[(size_t)i*WROW + 0] = 0.f;
  }
  if (t < 4) g_w[(size_t)i*WROW + 2*WIN + t] = 0.f;   // [128..131]
  if (t < BAND) g_w[(size_t)i*WROW + 1 + t] = valid ? (__expf(v - m) - c) : 0.f;
}

// ---------------------------------------------------------------------------
// K5: banded AFT core + sigmoid gate.
//   num[i,d] = c_i*Su[d] + sum_jj w[i][jj-i_local+1] * u_sh[jj][d]   (den with e, Se)
//   y = sigmoid(q) * num/den, written in place over g_q.
// Block: (i-tile of 32, batch); 256 threads (32 d-groups x 8 i-groups of 4 i).
// Dynamic smem: u window [158][128] + e window [158][128] + w tile [32][132].
// ---------------------------------------------------------------------------
__global__ void __launch_bounds__(256, 1) k_aft()
{
  extern __shared__ float dsm[];
  float* u_sh = dsm;
  float* e_sh = dsm + WR*DM;
  float* w_sh = dsm + 2*WR*DM;
  const int it = blockIdx.x, n = blockIdx.y;
  const int i0 = it*TI;
  const int j0 = i0 - (WIN-1);
  const int tid = threadIdx.x;

  const float* ug = g_v + (size_t)n*SL*DM;
  const float* eg = g_k + (size_t)n*SL*DM;
  for (int idx = tid; idx < WR*(DM/4); idx += 256){
    int row = idx >> 5, c4 = (idx & 31)*4;
    int j = j0 + row;
    float4 vu, ve;
    if (j >= 0 && j < SL){
      vu = *(const float4*)(ug + (size_t)j*DM + c4);
      ve = *(const float4*)(eg + (size_t)j*DM + c4);
    } else {
      vu = make_float4(0.f,0.f,0.f,0.f);
      ve = vu;
    }
    *(float4*)&u_sh[row*DM + c4] = vu;
    *(float4*)&e_sh[row*DM + c4] = ve;
  }
  for (int idx = tid; idx < TI*WROW; idx += 256)
    w_sh[idx] = g_w[(size_t)i0*WROW + idx];
  __syncthreads();

  const int dg = tid & 31, ig = tid >> 5;
  const int d0 = dg*4, ilb = ig*4;

  float2 Su0 = *(const float2*)(g_Su + n*DM + d0);
  float2 Su1 = *(const float2*)(g_Su + n*DM + d0 + 2);
  float2 Se0 = *(const float2*)(g_Se + n*DM + d0);
  float2 Se1 = *(const float2*)(g_Se + n*DM + d0 + 2);

  u64 an[4][2], ad[4][2];
  #pragma unroll
  for (int r = 0; r < 4; r++){
    float c = g_c[i0 + ilb + r];
    an[r][0] = pack2(c*Su0.x, c*Su0.y);
    an[r][1] = pack2(c*Su1.x, c*Su1.y);
    ad[r][0] = pack2(c*Se0.x, c*Se0.y);
    ad[r][1] = pack2(c*Se1.x, c*Se1.y);
  }

  const float* wb = w_sh + ilb*WROW;
  #pragma unroll 2
  for (int jj = 0; jj < WR; jj++){
    ulonglong2 uu = *(const ulonglong2*)(u_sh + jj*DM + d0);
    ulonglong2 ee = *(const ulonglong2*)(e_sh + jj*DM + d0);
    #pragma unroll
    for (int r = 0; r < 4; r++){
      int tw = jj - (ilb + r) + 1;
      tw = min(max(tw, 0), 2*WIN);            // clamp into padded row -> w=0 outside band
      u64 wd = pack_dup(wb[r*WROW + tw]);
      fma2(an[r][0], uu.x, wd);
      fma2(an[r][1], uu.y, wd);
      fma2(ad[r][0], ee.x, wd);
      fma2(ad[r][1], ee.y, wd);
    }
  }

  float* qp = g_q + (((size_t)n*SL + i0 + ilb)*DM + d0);
  #pragma unroll
  for (int r = 0; r < 4; r++){
    float4 q4 = *(const float4*)(qp + (size_t)r*DM);
    float2 n0 = unpack2(an[r][0]), n1 = unpack2(an[r][1]);
    float2 q0 = unpack2(ad[r][0]), q1 = unpack2(ad[r][1]);
    float4 y;
    y.x = __fdividef(1.f, 1.f + __expf(-q4.x)) * __fdividef(n0.x, q0.x);
    y.y = __fdividef(1.f, 1.f + __expf(-q4.y)) * __fdividef(n0.y, q0.y);
    y.z = __fdividef(1.f, 1.f + __expf(-q4.z)) * __fdividef(n1.x, q1.x);
    y.w = __fdividef(1.f, 1.f + __expf(-q4.w)) * __fdividef(n1.y, q1.y);
    *(float4*)(qp + (size_t)r*DM) = y;
  }
}

// ---------------------------------------------------------------------------
// K6: output projection + transpose to [n][c][l].
// Same FFMA2 GEMM structure as K1; input y[n,l,d] is loaded transposed into
// sh[c][li] as li-pairs; output staged through shared as [d][li] for coalesced
// row writes to d_out.
// ---------------------------------------------------------------------------
__global__ void __launch_bounds__(256, 2) k_oproj(
    const float* __restrict__ Wo, const float* __restrict__ bo,
    float* __restrict__ out)
{
  __shared__ float sh[DM*68];
  const int lt = blockIdx.x, n = blockIdx.y, l0 = lt*64, tid = threadIdx.x;

  // load y tile transposed: sh[c][li] with li-pairs packed per STS.64
  {
    const int lp = tid & 31;
    const int cg = tid >> 5;
    const float* yb = g_q + ((size_t)n*SL + l0)*DM;
    #pragma unroll
    for (int pass = 0; pass < 4; pass++){
      int c4 = cg + pass*8;                 // 0..31
      const float* ya = yb + (size_t)(2*lp)*DM + c4*4;
      float4 a = *(const float4*)ya;
      float4 b = *(const float4*)(ya + DM);
      *(float2*)&sh[(c4*4+0)*68 + 2*lp] = make_float2(a.x, b.x);
      *(float2*)&sh[(c4*4+1)*68 + 2*lp] = make_float2(a.y, b.y);
      *(float2*)&sh[(c4*4+2)*68 + 2*lp] = make_float2(a.z, b.z);
      *(float2*)&sh[(c4*4+3)*68 + 2*lp] = make_float2(a.w, b.w);
    }
  }
  __syncthreads();

  const int dg = tid & 31, lg = tid >> 5;
  const int d0 = dg*4, li0 = lg*8;
  u64 acc[4][4];
  #pragma unroll
  for (int a1=0;a1<4;a1++){
    #pragma unroll
    for (int b1=0;b1<4;b1++) acc[a1][b1] = 0ULL;
  }

  const float* Wp  = Wo + d0;
  const float* shx = sh + li0;
  #pragma unroll 4
  for (int c = 0; c < DM; c++){
    float4 w4 = *(const float4*)(Wp + (size_t)c*DM);
    u64 wd0 = pack_dup(w4.x), wd1 = pack_dup(w4.y), wd2 = pack_dup(w4.z), wd3 = pack_dup(w4.w);
    const u64* xp = (const u64*)(shx + c*68);
    u64 x0 = xp[0], x1 = xp[1], x2 = xp[2], x3 = xp[3];
    fma2(acc[0][0], x0, wd0); fma2(acc[0][1], x0, wd1); fma2(acc[0][2], x0, wd2); fma2(acc[0][3], x0, wd3);
    fma2(acc[1][0], x1, wd0); fma2(acc[1][1], x1, wd1); fma2(acc[1][2], x1, wd2); fma2(acc[1][3], x1, wd3);
    fma2(acc[2][0], x2, wd0); fma2(acc[2][1], x2, wd1); fma2(acc[2][2], x2, wd2); fma2(acc[2][3], x2, wd3);
    fma2(acc[3][0], x3, wd0); fma2(acc[3][1], x3, wd1); fma2(acc[3][2], x3, wd2); fma2(acc[3][3], x3, wd3);
  }
  __syncthreads();   // everyone done reading sh before reuse

  // stage outputs into sh[d][li]
  float4 b4 = *(const float4*)(bo + d0);
  #pragma unroll
  for (int pr = 0; pr < 4; pr++){
    float2 r0 = unpack2(acc[pr][0]);
    float2 r1 = unpack2(acc[pr][1]);
    float2 r2 = unpack2(acc[pr][2]);
    float2 r3 = unpack2(acc[pr][3]);
    *(float2*)&sh[(d0+0)*68 + li0 + 2*pr] = make_float2(r0.x+b4.x, r0.y+b4.x);
    *(float2*)&sh[(d0+1)*68 + li0 + 2*pr] = make_float2(r1.x+b4.y, r1.y+b4.y);
    *(float2*)&sh[(d0+2)*68 + li0 + 2*pr] = make_float2(r2.x+b4.z, r2.y+b4.z);
    *(float2*)&sh[(d0+3)*68 + li0 + 2*pr] = make_float2(r3.x+b4.w, r3.y+b4.w);
  }
  __syncthreads();

  // coalesced transposed store: out[n][d][l0..l0+63]
  float* ob = out + ((size_t)n*DM)*SL + l0;
  #pragma unroll
  for (int itr = 0; itr < 8; itr++){
    int idx = itr*256 + tid;
    int d = idx >> 4, l4 = (idx & 15)*4;
    float4 v4 = *(const float4*)&sh[d*68 + l4];
    *(float4*)(ob + (size_t)d*SL + l4) = v4;
  }
}

// ---------------------------------------------------------------------------
extern "C" void kernel_launch(void* const* d_in, const int* in_sizes, int n_in,
                              void* d_out, int out_size)
{
  const float* x  = (const float*)d_in[0];
  const float* Wq = (const float*)d_in[1];
  const float* bq = (const float*)d_in[2];
  const float* Wk = (const float*)d_in[3];
  const float* bk = (const float*)d_in[4];
  const float* Wv = (const float*)d_in[5];
  const float* bv = (const float*)d_in[6];
  const float* Wo = (const float*)d_in[7];
  const float* bo = (const float*)d_in[8];
  const float* pb = (const float*)d_in[9];
  float* out = (float*)d_out;

  cudaFuncSetAttribute(k_aft, cudaFuncAttributeMaxDynamicSharedMemorySize, AFT_SMEM);

  k_proj  <<<dim3(SL/64, NB, 3), 256>>>(x, Wq, bq, Wk, bk, Wv, bv);
  k_pb    <<<SL, 128>>>(pb);
  k_colmax<<<dim3(NB, NCH), 128>>>();
  k_colmax2<<<NB, 128>>>();
  k_expsum<<<dim3(NB, NCH), 128>>>();
  k_sum2  <<<NB, 128>>>();
  k_aft   <<<dim3(SL/TI, NB), 256, AFT_SMEM>>>();
  k_oproj <<<dim3(SL/64, NB), 256>>>(Wo, bo, out);
}